// round 6
// baseline (speedup 1.0000x reference)
#include <cuda_runtime.h>
#include <cuda_bf16.h>

// LIF neuron forward: T=8 timesteps, N = B*C*H*W = 4,194,304 elems/timestep.
//   mem = 0.5*(mem + x[t]); spike = (mem > 0.5); mem = spike ? 0 : mem;
// Output spike[t][i] as float32, layout identical to input.
//
// HBM-bound streaming kernel (128 MB in + 128 MB out, zero reuse).
// R1 was 36.9us @ 73.7% DRAM. Changes this round (5th submit; R2-R5 hit infra
// GPU-acquisition timeouts, kernel never ran):
//  - grid-stride loop at exactly 148*8 CTAs (perfect wave balance, no tail)
//  - software pipeline over t with prefetch distance 2 (MLP_p1=2 per thread;
//    latency hiding comes from TLP, flattening cross-CTA L1tex-queue spread)
//  - __ldcs/__stcs streaming hints (evict-first; no L2 pollution)

#define T_STEPS 8
#define N_ELEMS (32 * 128 * 32 * 32)
#define N_VEC   (N_ELEMS / 4)           // 1,048,576 float4 slots per timestep
#define NUM_CTAS (148 * 8)              // 1184: one full-occupancy wave
#define THREADS 256

__device__ __forceinline__ float4 lif_step(float4& mem, float4 xt)
{
    float4 sp;
    mem.x = 0.5f * (mem.x + xt.x);
    mem.y = 0.5f * (mem.y + xt.y);
    mem.z = 0.5f * (mem.z + xt.z);
    mem.w = 0.5f * (mem.w + xt.w);
    sp.x = (mem.x > 0.5f) ? 1.0f : 0.0f;
    sp.y = (mem.y > 0.5f) ? 1.0f : 0.0f;
    sp.z = (mem.z > 0.5f) ? 1.0f : 0.0f;
    sp.w = (mem.w > 0.5f) ? 1.0f : 0.0f;
    mem.x = (sp.x != 0.0f) ? 0.0f : mem.x;
    mem.y = (sp.y != 0.0f) ? 0.0f : mem.y;
    mem.z = (sp.z != 0.0f) ? 0.0f : mem.z;
    mem.w = (sp.w != 0.0f) ? 0.0f : mem.w;
    return sp;
}

__global__ __launch_bounds__(THREADS) void lif_forward_kernel(
    const float4* __restrict__ x, float4* __restrict__ out)
{
    const int stride = NUM_CTAS * THREADS;

    for (int i = blockIdx.x * THREADS + threadIdx.x; i < N_VEC; i += stride) {
        // Software pipeline over timesteps, prefetch distance 2.
        float4 a = __ldcs(&x[0 * N_VEC + i]);
        float4 b = __ldcs(&x[1 * N_VEC + i]);

        float4 mem = make_float4(0.f, 0.f, 0.f, 0.f);

#pragma unroll
        for (int t = 0; t < T_STEPS; ++t) {
            float4 cur = a;
            a = b;
            if (t + 2 < T_STEPS) {
                b = __ldcs(&x[(t + 2) * N_VEC + i]);
            }
            float4 sp = lif_step(mem, cur);
            __stcs(&out[t * N_VEC + i], sp);
        }
    }
}

extern "C" void kernel_launch(void* const* d_in, const int* in_sizes, int n_in,
                              void* d_out, int out_size)
{
    const float4* x = (const float4*)d_in[0];
    float4* out = (float4*)d_out;
    lif_forward_kernel<<<NUM_CTAS, THREADS>>>(x, out);
}